// round 15
// baseline (speedup 1.0000x reference)
#include <cuda_runtime.h>
#include <cuda_fp16.h>
#include <math.h>

#define MAXB 16384
#define DT 0.01f
#define FULLMASK 0xffffffffu
#define TRI(i,j) ((i)*((i)+1)/2+(j))

__constant__ float c_LOWER[6] = {-6.28f,-6.28f,-3.14f,-6.28f,-6.28f,-6.28f};
__constant__ float c_UPPER[6] = { 6.28f, 6.28f, 3.14f, 6.28f, 6.28f, 6.28f};
__constant__ float c_EFFORT[6]= {150.f,150.f,150.f,28.f,28.f,28.f};

__device__ float g_qs [4][MAXB*6];
__device__ float g_qds[4][MAXB*6];
__device__ float g_kqd[3][MAXB*6];
__device__ int   g_viol[4];

// fp16 B fragments for mma.m16n8k16
__device__ uint2 g_W1L [128*4];
__device__ uint2 g_W2L [128*8*4];
__device__ uint2 g_W3L [24*8*4];
__device__ uint2 g_W1V [128*4];
__device__ uint2 g_W2V [128*8*4];
__device__ uint2 g_W2VT[128*8*4];
__device__ uint2 g_W1VT[16*8*4];

__device__ __forceinline__ float sp_f(float x){ return fmaxf(x,0.f)+__logf(1.f+__expf(-fabsf(x))); }
__device__ __forceinline__ float sg_f(float x){ return __fdividef(1.f,1.f+__expf(-x)); }
__device__ __forceinline__ void mma16(float*d,unsigned a0,unsigned a1,unsigned a2,unsigned a3,unsigned b0,unsigned b1){
  asm volatile("mma.sync.aligned.m16n8k16.row.col.f32.f16.f16.f32 "
    "{%0,%1,%2,%3},{%4,%5,%6,%7},{%8,%9},{%0,%1,%2,%3};"
    :"+f"(d[0]),"+f"(d[1]),"+f"(d[2]),"+f"(d[3])
    :"r"(a0),"r"(a1),"r"(a2),"r"(a3),"r"(b0),"r"(b1));
}
__device__ __forceinline__ void ldsm4(unsigned&r0,unsigned&r1,unsigned&r2,unsigned&r3,unsigned a){
  asm volatile("ldmatrix.sync.aligned.m8n8.x4.shared.b16 {%0,%1,%2,%3},[%4];"
    :"=r"(r0),"=r"(r1),"=r"(r2),"=r"(r3):"r"(a));
}
// 128-half rows (256B stride), 16B-segment XOR swizzle
__device__ __forceinline__ int hswz(int r,int c){ return r*256 + ((((c>>3)^(r&7)))<<4) + ((c&7)<<1); }
__device__ __forceinline__ uint2 packb(float a,float b,float c,float d){
  __half2 h0=__floats2half2_rn(a,b), h1=__floats2half2_rn(c,d);
  uint2 u; u.x=*(unsigned*)&h0; u.y=*(unsigned*)&h1; return u;
}

__global__ void zero_viol_kernel(){ if (threadIdx.x<4) g_viol[threadIdx.x]=0; }

// weights prep + stage-0 kinematics + viol[0]
__global__ void init_kernel(const float* __restrict__ obs,
    const float* __restrict__ W1L,const float* __restrict__ b1L,
    const float* __restrict__ W2L,const float* __restrict__ W3L,
    const float* __restrict__ W1V,const float* __restrict__ b1V,const float* __restrict__ W2V,
    int B){
  int i=blockIdx.x*blockDim.x+threadIdx.x;
  if (i<512){
    int n=i>>2, tig=i&3; int k0=2*tig;
    int ks[4]={k0,k0+1,k0+8,k0+9}; float v[4];
#pragma unroll
    for(int t=0;t<4;t++){ int k=ks[t]; v[t]=(k<12)?W1L[n*12+k]:((k==12)?b1L[n]:0.f); }
    g_W1L[i]=packb(v[0],v[1],v[2],v[3]);
  } else if (i<4608){ int j=i-512; int n=j>>5, ktp=(j>>2)&7, tig=j&3; int k0=ktp*16+2*tig;
    g_W2L[j]=packb(W2L[n*128+k0],W2L[n*128+k0+1],W2L[n*128+k0+8],W2L[n*128+k0+9]);
  } else if (i<5376){ int j=i-4608; int n=j>>5, ktp=(j>>2)&7, tig=j&3; int k0=ktp*16+2*tig;
    if (n<21) g_W3L[j]=packb(W3L[n*128+k0],W3L[n*128+k0+1],W3L[n*128+k0+8],W3L[n*128+k0+9]);
    else      g_W3L[j]=packb(0.f,0.f,0.f,0.f);
  } else if (i<5888){ int j=i-5376;
    int n=j>>2, tig=j&3; int k0=2*tig;
    int ks[4]={k0,k0+1,k0+8,k0+9}; float v[4];
#pragma unroll
    for(int t=0;t<4;t++){ int k=ks[t]; v[t]=(k<12)?W1V[n*12+k]:((k==12)?b1V[n]:0.f); }
    g_W1V[j]=packb(v[0],v[1],v[2],v[3]);
  } else if (i<9984){ int j=i-5888; int n=j>>5, ktp=(j>>2)&7, tig=j&3; int k0=ktp*16+2*tig;
    g_W2V[j]=packb(W2V[n*128+k0],W2V[n*128+k0+1],W2V[n*128+k0+8],W2V[n*128+k0+9]);
  } else if (i<14080){ int j=i-9984; int n=j>>5, ktp=(j>>2)&7, tig=j&3; int k0=ktp*16+2*tig;
    g_W2VT[j]=packb(W2V[k0*128+n],W2V[(k0+1)*128+n],W2V[(k0+8)*128+n],W2V[(k0+9)*128+n]);
  } else if (i<14592){ int j=i-14080; int n=j>>5, ktp=(j>>2)&7, tig=j&3; int k0=ktp*16+2*tig;
    if (n<12) g_W1VT[j]=packb(W1V[k0*12+n],W1V[(k0+1)*12+n],W1V[(k0+8)*12+n],W1V[(k0+9)*12+n]);
    else      g_W1VT[j]=packb(0.f,0.f,0.f,0.f);
  }
  unsigned b0=0;
  if (i<B*6){
    int e=i/6, j=i-e*6;
    float q0=obs[e*12+j], qd0=obs[e*12+6+j];
    g_qs[0][i]=q0; g_qds[0][i]=qd0;
    float lo=c_LOWER[j]+0.1f, up=c_UPPER[j]-0.1f;
    if (q0<=lo || q0>=up) b0=1u<<j;
  }
  unsigned r0=__reduce_or_sync(FULLMASK,b0);
  if ((threadIdx.x&31)==0 && r0) atomicOr(&g_viol[0],(int)r0);
}

// smem layout (bytes)
#define BA0   0
#define BVIN  5376
#define BH    6144
#define BH1V  34816
#define BR2   38912
#define BSL   43008
#define BSG   54272
#define SMEM_BYTES 57344
#define WSL (BSL/4)
#define WSG (BSG/4)

__global__ void __launch_bounds__(256,2)
accel_mma_kernel(int S, const float* __restrict__ obs, const float* __restrict__ action,
    float* __restrict__ out,
    const float* __restrict__ b2L, const float* __restrict__ b3L,
    const float* __restrict__ b2V, const float* __restrict__ W3V, int B)
{
  extern __shared__ char smc[];
  float* smf=(float*)smc;
  const int tid=threadIdx.x, w=tid>>5, lane=tid&31;
  const int gid=lane>>2, tig=lane&3;
  const int eb=blockIdx.x*16;
  const int vm=g_viol[S];
  const unsigned smb=(unsigned)__cvta_generic_to_shared(smc);

  const int sub=lane>>3, l7=lane&7;
  const int lm_row=l7+((sub&1)<<3);
  const int chunk=sub>>1;
  const int r7=l7;
  const unsigned aA0 = smb + BA0 + lm_row*48 + chunk*16;
  const unsigned aVIN= smb + BVIN + lm_row*48 + chunk*16;
  const unsigned rbH  = smb + BH   + lm_row*256;
  const unsigned rbH1V= smb + BH1V + lm_row*256;
  const unsigned rbR2 = smb + BR2  + lm_row*256;

  // ---------- P0: build A matrices (row = ch*16 + el) ----------
  if (tid<112){
    int row=tid, ch=row>>4, el=row&15;
    int e=eb+el; if (e>=B) e=B-1;
    float t16[16];
#pragma unroll
    for(int k=0;k<16;k++) t16[k]=0.f;
    if (ch==0){
#pragma unroll
      for(int j=0;j<6;j++){ float qj=g_qs[S][e*6+j]; t16[2*j]=cosf(qj); t16[2*j+1]=sinf(qj); }
      t16[12]=1.f;
    } else {
      int p=ch-1; float qp=g_qs[S][e*6+p];
      t16[2*p]=-sinf(qp); t16[2*p+1]=cosf(qp);
    }
    __half2* dst=(__half2*)(smc+BA0+row*48);
#pragma unroll
    for(int k=0;k<8;k++) dst[k]=__floats2half2_rn(t16[2*k],t16[2*k+1]);
    if (ch==0){
      __half2* dv=(__half2*)(smc+BVIN+el*48);
#pragma unroll
      for(int k=0;k<8;k++) dv[k]=__floats2half2_rn(t16[2*k],t16[2*k+1]);
    }
  }
  __syncthreads();

  // ---------- P1: V layer1 + L layer1 (K=16) ----------
  {
    float DV[2][4]={};
    {
      unsigned a0,a1,a2,a3; ldsm4(a0,a1,a2,a3,aVIN);
#pragma unroll
      for(int nt=0;nt<2;nt++){
        uint2 bf=__ldg(&g_W1V[(w*16+nt*8+gid)*4+tig]);
        mma16(DV[nt],a0,a1,a2,a3,bf.x,bf.y);
      }
    }
#pragma unroll
    for(int nt=0;nt<2;nt++){
      int c0=w*16+nt*8+tig*2;
      *(__half2*)(smc+BH1V+hswz(gid,c0))  =__floats2half2_rn(sp_f(DV[nt][0]),sp_f(DV[nt][1]));
      *(__half2*)(smc+BH1V+hswz(gid+8,c0))=__floats2half2_rn(sp_f(DV[nt][2]),sp_f(DV[nt][3]));
    }
    float D1[7][2][4]={};
#pragma unroll
    for(int m=0;m<7;m++){
      unsigned a0,a1,a2,a3; ldsm4(a0,a1,a2,a3,aA0+m*768);
#pragma unroll
      for(int nt=0;nt<2;nt++){
        uint2 bf=__ldg(&g_W1L[(w*16+nt*8+gid)*4+tig]);
        mma16(D1[m][nt],a0,a1,a2,a3,bf.x,bf.y);
      }
    }
    float sgr[2][4];
#pragma unroll
    for(int nt=0;nt<2;nt++){
      int c0=w*16+nt*8+tig*2;
#pragma unroll
      for(int i=0;i<4;i++) sgr[nt][i]=sg_f(D1[0][nt][i]);
      *(__half2*)(smc+BH+hswz(gid,c0))  =__floats2half2_rn(sp_f(D1[0][nt][0]),sp_f(D1[0][nt][1]));
      *(__half2*)(smc+BH+hswz(gid+8,c0))=__floats2half2_rn(sp_f(D1[0][nt][2]),sp_f(D1[0][nt][3]));
    }
#pragma unroll
    for(int m=1;m<7;m++)
#pragma unroll
      for(int nt=0;nt<2;nt++){
        int c0=w*16+nt*8+tig*2;
        *(__half2*)(smc+BH+hswz(m*16+gid,c0))  =__floats2half2_rn(sgr[nt][0]*D1[m][nt][0],sgr[nt][1]*D1[m][nt][1]);
        *(__half2*)(smc+BH+hswz(m*16+8+gid,c0))=__floats2half2_rn(sgr[nt][2]*D1[m][nt][2],sgr[nt][3]*D1[m][nt][3]);
      }
  }
  __syncthreads();

  // ---------- P2: merged V layer2 + L layer2 GEMM (one ktp loop, more ILP) ----------
  {
    float DV[2][4]={};
    float D2[7][2][4]={};
#pragma unroll 2
    for(int ktp=0;ktp<8;ktp++){
      unsigned koff=(((unsigned)(2*ktp+chunk)^r7)<<4);
      unsigned v0,v1,v2,v3; ldsm4(v0,v1,v2,v3, rbH1V + koff);
      uint2 bfv[2], bfl[2];
#pragma unroll
      for(int nt=0;nt<2;nt++){
        bfv[nt]=__ldg(&g_W2V[((w*16+nt*8+gid)*8+ktp)*4+tig]);
        bfl[nt]=__ldg(&g_W2L[((w*16+nt*8+gid)*8+ktp)*4+tig]);
      }
#pragma unroll
      for(int nt=0;nt<2;nt++) mma16(DV[nt],v0,v1,v2,v3,bfv[nt].x,bfv[nt].y);
#pragma unroll
      for(int m=0;m<7;m++){
        unsigned a0,a1,a2,a3; ldsm4(a0,a1,a2,a3, rbH + m*4096 + koff);
#pragma unroll
        for(int nt=0;nt<2;nt++) mma16(D2[m][nt],a0,a1,a2,a3,bfl[nt].x,bfl[nt].y);
      }
    }
    // V epilogue -> R2
#pragma unroll
    for(int nt=0;nt<2;nt++){
      int c0=w*16+nt*8+tig*2;
      float bv0=__ldg(b2V+c0),bv1=__ldg(b2V+c0+1),w30=__ldg(W3V+c0),w31=__ldg(W3V+c0+1);
      *(__half2*)(smc+BR2+hswz(gid,c0))  =__floats2half2_rn(w30*sg_f(DV[nt][0]+bv0),w31*sg_f(DV[nt][1]+bv1));
      *(__half2*)(smc+BR2+hswz(gid+8,c0))=__floats2half2_rn(w30*sg_f(DV[nt][2]+bv0),w31*sg_f(DV[nt][3]+bv1));
    }
    __syncthreads();   // all warps done reading H (and R2 written)
    // L epilogue -> H (in place)
    float sgr[2][4];
#pragma unroll
    for(int nt=0;nt<2;nt++){
      int c0=w*16+nt*8+tig*2;
      float b0=__ldg(b2L+c0), b1=__ldg(b2L+c0+1);
      float z0=D2[0][nt][0]+b0, z1=D2[0][nt][1]+b1, z2=D2[0][nt][2]+b0, z3=D2[0][nt][3]+b1;
      sgr[nt][0]=sg_f(z0); sgr[nt][1]=sg_f(z1); sgr[nt][2]=sg_f(z2); sgr[nt][3]=sg_f(z3);
      *(__half2*)(smc+BH+hswz(gid,c0))  =__floats2half2_rn(sp_f(z0),sp_f(z1));
      *(__half2*)(smc+BH+hswz(gid+8,c0))=__floats2half2_rn(sp_f(z2),sp_f(z3));
    }
#pragma unroll
    for(int m=1;m<7;m++)
#pragma unroll
      for(int nt=0;nt<2;nt++){
        int c0=w*16+nt*8+tig*2;
        *(__half2*)(smc+BH+hswz(m*16+gid,c0))  =__floats2half2_rn(sgr[nt][0]*D2[m][nt][0],sgr[nt][1]*D2[m][nt][1]);
        *(__half2*)(smc+BH+hswz(m*16+8+gid,c0))=__floats2half2_rn(sgr[nt][2]*D2[m][nt][2],sgr[nt][3]*D2[m][nt][3]);
      }
  }
  __syncthreads();

  // ---------- P3: L layer3 (w0-2) | merged V backward + K-split grad (w4-7) ----------
  if (w<3){
    float D3[7][4]={};
#pragma unroll 2
    for(int ktp=0;ktp<8;ktp++){
      uint2 bf=__ldg(&g_W3L[((w*8+gid)*8+ktp)*4+tig]);
      unsigned koff=(((unsigned)(2*ktp+chunk)^r7)<<4);
#pragma unroll
      for(int m=0;m<7;m++){
        unsigned a0,a1,a2,a3; ldsm4(a0,a1,a2,a3, rbH + m*4096 + koff);
        mma16(D3[m],a0,a1,a2,a3,bf.x,bf.y);
      }
    }
    int c0=w*8+tig*2;
    float bb0=(c0<21)?__ldg(b3L+c0):0.f, bb1=(c0+1<21)?__ldg(b3L+c0+1):0.f;
    float z0=D3[0][0]+bb0, z1=D3[0][1]+bb1, z2=D3[0][2]+bb0, z3=D3[0][3]+bb1;
    float sg0=sg_f(z0),sg1=sg_f(z1),sg2=sg_f(z2),sg3=sg_f(z3);
    smf[WSL+gid*176+c0]=sp_f(z0);      smf[WSL+gid*176+c0+1]=sp_f(z1);
    smf[WSL+(gid+8)*176+c0]=sp_f(z2);  smf[WSL+(gid+8)*176+c0+1]=sp_f(z3);
#pragma unroll
    for(int m=1;m<7;m++){
      smf[WSL+gid*176+m*25+c0]=sg0*D3[m][0];      smf[WSL+gid*176+m*25+c0+1]=sg1*D3[m][1];
      smf[WSL+(gid+8)*176+m*25+c0]=sg2*D3[m][2];  smf[WSL+(gid+8)*176+m*25+c0+1]=sg3*D3[m][3];
    }
  } else if (w>=4){
    const int wv=w-4;
    float DB[4][4]={};
#pragma unroll 2
    for(int ktp=0;ktp<8;ktp++){
      unsigned a0,a1,a2,a3; ldsm4(a0,a1,a2,a3, rbR2 + (((2*ktp+chunk)^r7)<<4));
#pragma unroll
      for(int nt=0;nt<4;nt++){
        int n=wv*32+nt*8+gid;
        uint2 bf=__ldg(&g_W2VT[(n*8+ktp)*4+tig]);
        mma16(DB[nt],a0,a1,a2,a3,bf.x,bf.y);
      }
    }
#pragma unroll
    for(int nt=0;nt<4;nt++){
      int c0=wv*32+nt*8+tig*2;
      float2 hA=__half22float2(*(__half2*)(smc+BH1V+hswz(gid,c0)));
      float2 hB=__half22float2(*(__half2*)(smc+BH1V+hswz(gid+8,c0)));
      float r0=DB[nt][0]*(1.f-__expf(-hA.x)), r1=DB[nt][1]*(1.f-__expf(-hA.y));
      float r2=DB[nt][2]*(1.f-__expf(-hB.x)), r3=DB[nt][3]*(1.f-__expf(-hB.y));
      *(__half2*)(smc+BH1V+hswz(gid,c0))  =__floats2half2_rn(r0,r1);
      *(__half2*)(smc+BH1V+hswz(gid+8,c0))=__floats2half2_rn(r2,r3);
    }
    __syncwarp();
    // K-split grad partial: this warp's 32 K-columns (ktp = 2wv, 2wv+1)
    float DG[2][4]={};
#pragma unroll
    for(int t=0;t<2;t++){
      int ktp=2*wv+t;
      unsigned a0,a1,a2,a3; ldsm4(a0,a1,a2,a3, rbH1V + (((2*ktp+chunk)^r7)<<4));
#pragma unroll
      for(int nt=0;nt<2;nt++){
        uint2 bf=__ldg(&g_W1VT[((nt*8+gid)*8+ktp)*4+tig]);
        mma16(DG[nt],a0,a1,a2,a3,bf.x,bf.y);
      }
    }
#pragma unroll
    for(int nt=0;nt<2;nt++){
      int c=nt*8+tig*2;
      if (c<12){ smf[WSG+wv*192+gid*12+c]=DG[nt][0]; smf[WSG+wv*192+(gid+8)*12+c]=DG[nt][2]; }
      if (c+1<12){ smf[WSG+wv*192+gid*12+c+1]=DG[nt][1]; smf[WSG+wv*192+(gid+8)*12+c+1]=DG[nt][3]; }
    }
  }
  __syncthreads();

  // ---------- P5: assembly + Cholesky solve (warps 0-3, 8 lanes/element) ----------
  if (w<4){
    int gl=lane&7, grp=lane>>3, eloc=w*4+grp;
    int e=eb+eloc; bool valid=(e<B); if(!valid) e=B-1;
    const float* SLe=smf+WSL+eloc*176;
    float* SDel=smf+eloc*24;
    float qd6[6];
#pragma unroll
    for(int j=0;j<6;j++) qd6[j]=g_qds[S][e*6+j];
    if (gl<7){
#pragma unroll
      for(int t=0;t<3;t++){
        int m=gl*3+t;
        if (m<21){
          float s=0.f;
#pragma unroll
          for(int p=0;p<6;p++) s+=qd6[p]*SLe[(1+p)*25+m];
          SDel[m]=s;
        }
      }
    }
    __syncwarp();
    int li=(gl<6)?gl:5;
    float w6[6],u6[6],Dq[6];
#pragma unroll
    for(int k=0;k<6;k++){
      float sw=0.f,su=0.f,sd=0.f;
#pragma unroll
      for(int i2=0;i2<6;i2++) if (i2>=k){
        int m=TRI(i2,k); float a=qd6[i2];
        sw+=SLe[m]*a; su+=SLe[(1+li)*25+m]*a; sd+=SDel[m]*a;
      }
      w6[k]=sw; u6[k]=su; Dq[k]=sd;
    }
    float term2=0.f;
#pragma unroll
    for(int k=0;k<6;k++) term2+=w6[k]*u6[k];
    int base=li*(li+1)/2;
    float Dw=0.f,LDq=0.f;
#pragma unroll
    for(int j2=0;j2<6;j2++) if (j2<=li){ Dw+=SDel[base+j2]*w6[j2]; LDq+=SLe[base+j2]*Dq[j2]; }
    float ci=Dw+LDq-term2;
    float qsi=g_qs[S][e*6+li];
    float gx=0.f,gy=0.f;
#pragma unroll
    for(int p=0;p<4;p++){ gx+=smf[WSG+p*192+eloc*12+2*li]; gy+=smf[WSG+p*192+eloc*12+2*li+1]; }
    float gi=-gx*sinf(qsi)+gy*cosf(qsi);
    float lo=c_LOWER[li]+0.1f, up=c_UPPER[li]-0.1f;
    float fi;
    if ((vm>>li)&1) fi=(qsi<=lo)?c_EFFORT[li]:((qsi>=up)?-c_EFFORT[li]:0.f);
    else            fi=-5.f*(1.f/(qsi-lo)-1.f/(up-qsi));
    float tau=__ldg(action+e*6+li)*c_EFFORT[li];
    float rhs=tau-ci-gi-fi;
    int gb=lane&~7;
    float accf=rhs, yvv=0.f;
#pragma unroll
    for(int j2=0;j2<6;j2++){
      float yj=__shfl_sync(FULLMASK,accf,gb+j2)/SLe[TRI(j2,j2)];
      if (gl==j2) yvv=yj;
      if (gl>j2 && gl<6) accf-=SLe[base+j2]*yj;
    }
    float acc2=yvv, xi=0.f;
#pragma unroll
    for(int j2=5;j2>=0;j2--){
      float xj=__shfl_sync(FULLMASK,acc2,gb+j2)/SLe[TRI(j2,j2)];
      if (gl==j2) xi=xj;
      if (gl<j2) acc2-=SLe[TRI(j2,gl)]*xj;
    }

    if (S<3){
      if (gl<6 && valid) g_kqd[S][e*6+gl]=xi;
      unsigned bits=0;
      if (gl<6 && valid){
        float q0=obs[e*12+gl], qd0=obs[e*12+6+gl];
        float qs,qds;
        if (S==0){ qs=q0+0.5f*DT*qd0;                 qds=qd0+0.5f*DT*xi; }
        else if (S==1){ qs=q0+0.5f*DT*g_qds[1][e*6+gl]; qds=qd0+0.5f*DT*xi; }
        else          { qs=q0+DT*g_qds[2][e*6+gl];      qds=qd0+DT*xi; }
        g_qs[S+1][e*6+gl]=qs; g_qds[S+1][e*6+gl]=qds;
        float lo2=c_LOWER[gl]+0.1f, up2=c_UPPER[gl]-0.1f;
        if (qs<=lo2 || qs>=up2) bits=1u<<gl;
      }
      unsigned r=__reduce_or_sync(FULLMASK,bits);
      if (lane==0 && r) atomicOr(&g_viol[S+1],(int)r);
    } else {
      if (gl<6 && valid){
        int idx=e*6+gl;
        float q0=obs[e*12+gl], qd0=obs[e*12+6+gl];
        float k0=g_kqd[0][idx],k1=g_kqd[1][idx],k2=g_kqd[2][idx];
        const float c1=DT/6.f;
        float qn=q0+c1*(g_qds[0][idx]+2.f*g_qds[1][idx]+2.f*g_qds[2][idx]+g_qds[3][idx]);
        qn=fminf(fmaxf(qn,c_LOWER[gl]),c_UPPER[gl]);
        float qdn=qd0+c1*(k0+2.f*k1+2.f*k2+xi);
        out[e*12+gl]=qn;
        out[e*12+6+gl]=qdn;
      }
    }
  }
}

extern "C" void kernel_launch(void* const* d_in, const int* in_sizes, int n_in,
                              void* d_out, int out_size)
{
  const float* obs   =(const float*)d_in[0];
  const float* action=(const float*)d_in[1];
  const float* W1L=(const float*)d_in[2];  const float* b1L=(const float*)d_in[3];
  const float* W2L=(const float*)d_in[4];  const float* b2L=(const float*)d_in[5];
  const float* W3L=(const float*)d_in[6];  const float* b3L=(const float*)d_in[7];
  const float* W1V=(const float*)d_in[8];  const float* b1V=(const float*)d_in[9];
  const float* W2V=(const float*)d_in[10]; const float* b2V=(const float*)d_in[11];
  const float* W3V=(const float*)d_in[12]; const float* b3V=(const float*)d_in[13];
  (void)b3V;
  float* out=(float*)d_out;
  int B=in_sizes[0]/12;
  if (B>MAXB) B=MAXB;

  cudaFuncSetAttribute(accel_mma_kernel, cudaFuncAttributeMaxDynamicSharedMemorySize, SMEM_BYTES);

  int nbA=(B+15)/16;
  int nbI=(B*6+255)/256; if (nbI<57) nbI=57;

  zero_viol_kernel<<<1,32>>>();
  init_kernel<<<nbI,256>>>(obs,W1L,b1L,W2L,W3L,W1V,b1V,W2V,B);
  for (int s=0;s<4;s++){
    accel_mma_kernel<<<nbA,256,SMEM_BYTES>>>(s,obs,action,out,b2L,b3L,b2V,W3V,B);
  }
}

// round 16
// speedup vs baseline: 1.0169x; 1.0169x over previous
#include <cuda_runtime.h>
#include <cuda_fp16.h>
#include <math.h>

#define MAXB 16384
#define DT 0.01f
#define FULLMASK 0xffffffffu
#define TRI(i,j) ((i)*((i)+1)/2+(j))

__constant__ float c_LOWER[6] = {-6.28f,-6.28f,-3.14f,-6.28f,-6.28f,-6.28f};
__constant__ float c_UPPER[6] = { 6.28f, 6.28f, 3.14f, 6.28f, 6.28f, 6.28f};
__constant__ float c_EFFORT[6]= {150.f,150.f,150.f,28.f,28.f,28.f};

__device__ float g_qs [4][MAXB*6];
__device__ float g_qds[4][MAXB*6];
__device__ float g_kqd[3][MAXB*6];
__device__ int   g_viol[4];

// fp16 B fragments for mma.m16n8k16
__device__ uint2 g_W1L [128*4];
__device__ uint2 g_W2L [128*8*4];
__device__ uint2 g_W3L [24*8*4];
__device__ uint2 g_W1V [128*4];
__device__ uint2 g_W2V [128*8*4];
__device__ uint2 g_W2VT[128*8*4];
__device__ uint2 g_W1VT[16*8*4];

__device__ __forceinline__ float sp_f(float x){ return fmaxf(x,0.f)+__logf(1.f+__expf(-fabsf(x))); }
__device__ __forceinline__ float sg_f(float x){ return __fdividef(1.f,1.f+__expf(-x)); }
__device__ __forceinline__ void mma16(float*d,unsigned a0,unsigned a1,unsigned a2,unsigned a3,unsigned b0,unsigned b1){
  asm volatile("mma.sync.aligned.m16n8k16.row.col.f32.f16.f16.f32 "
    "{%0,%1,%2,%3},{%4,%5,%6,%7},{%8,%9},{%0,%1,%2,%3};"
    :"+f"(d[0]),"+f"(d[1]),"+f"(d[2]),"+f"(d[3])
    :"r"(a0),"r"(a1),"r"(a2),"r"(a3),"r"(b0),"r"(b1));
}
__device__ __forceinline__ void ldsm4(unsigned&r0,unsigned&r1,unsigned&r2,unsigned&r3,unsigned a){
  asm volatile("ldmatrix.sync.aligned.m8n8.x4.shared.b16 {%0,%1,%2,%3},[%4];"
    :"=r"(r0),"=r"(r1),"=r"(r2),"=r"(r3):"r"(a));
}
// 128-half rows (256B stride), 16B-segment XOR swizzle
__device__ __forceinline__ int hswz(int r,int c){ return r*256 + ((((c>>3)^(r&7)))<<4) + ((c&7)<<1); }
__device__ __forceinline__ uint2 packb(float a,float b,float c,float d){
  __half2 h0=__floats2half2_rn(a,b), h1=__floats2half2_rn(c,d);
  uint2 u; u.x=*(unsigned*)&h0; u.y=*(unsigned*)&h1; return u;
}

__global__ void zero_viol_kernel(){ if (threadIdx.x<4) g_viol[threadIdx.x]=0; }

// weights prep + stage-0 kinematics + viol[0]
__global__ void init_kernel(const float* __restrict__ obs,
    const float* __restrict__ W1L,const float* __restrict__ b1L,
    const float* __restrict__ W2L,const float* __restrict__ W3L,
    const float* __restrict__ W1V,const float* __restrict__ b1V,const float* __restrict__ W2V,
    int B){
  int i=blockIdx.x*blockDim.x+threadIdx.x;
  if (i<512){
    int n=i>>2, tig=i&3; int k0=2*tig;
    int ks[4]={k0,k0+1,k0+8,k0+9}; float v[4];
#pragma unroll
    for(int t=0;t<4;t++){ int k=ks[t]; v[t]=(k<12)?W1L[n*12+k]:((k==12)?b1L[n]:0.f); }
    g_W1L[i]=packb(v[0],v[1],v[2],v[3]);
  } else if (i<4608){ int j=i-512; int n=j>>5, ktp=(j>>2)&7, tig=j&3; int k0=ktp*16+2*tig;
    g_W2L[j]=packb(W2L[n*128+k0],W2L[n*128+k0+1],W2L[n*128+k0+8],W2L[n*128+k0+9]);
  } else if (i<5376){ int j=i-4608; int n=j>>5, ktp=(j>>2)&7, tig=j&3; int k0=ktp*16+2*tig;
    if (n<21) g_W3L[j]=packb(W3L[n*128+k0],W3L[n*128+k0+1],W3L[n*128+k0+8],W3L[n*128+k0+9]);
    else      g_W3L[j]=packb(0.f,0.f,0.f,0.f);
  } else if (i<5888){ int j=i-5376;
    int n=j>>2, tig=j&3; int k0=2*tig;
    int ks[4]={k0,k0+1,k0+8,k0+9}; float v[4];
#pragma unroll
    for(int t=0;t<4;t++){ int k=ks[t]; v[t]=(k<12)?W1V[n*12+k]:((k==12)?b1V[n]:0.f); }
    g_W1V[j]=packb(v[0],v[1],v[2],v[3]);
  } else if (i<9984){ int j=i-5888; int n=j>>5, ktp=(j>>2)&7, tig=j&3; int k0=ktp*16+2*tig;
    g_W2V[j]=packb(W2V[n*128+k0],W2V[n*128+k0+1],W2V[n*128+k0+8],W2V[n*128+k0+9]);
  } else if (i<14080){ int j=i-9984; int n=j>>5, ktp=(j>>2)&7, tig=j&3; int k0=ktp*16+2*tig;
    g_W2VT[j]=packb(W2V[k0*128+n],W2V[(k0+1)*128+n],W2V[(k0+8)*128+n],W2V[(k0+9)*128+n]);
  } else if (i<14592){ int j=i-14080; int n=j>>5, ktp=(j>>2)&7, tig=j&3; int k0=ktp*16+2*tig;
    if (n<12) g_W1VT[j]=packb(W1V[k0*12+n],W1V[(k0+1)*12+n],W1V[(k0+8)*12+n],W1V[(k0+9)*12+n]);
    else      g_W1VT[j]=packb(0.f,0.f,0.f,0.f);
  }
  unsigned b0=0;
  if (i<B*6){
    int e=i/6, j=i-e*6;
    float q0=obs[e*12+j], qd0=obs[e*12+6+j];
    g_qs[0][i]=q0; g_qds[0][i]=qd0;
    float lo=c_LOWER[j]+0.1f, up=c_UPPER[j]-0.1f;
    if (q0<=lo || q0>=up) b0=1u<<j;
  }
  unsigned r0=__reduce_or_sync(FULLMASK,b0);
  if ((threadIdx.x&31)==0 && r0) atomicOr(&g_viol[0],(int)r0);
}

// smem layout (bytes)
#define BA0   0
#define BVIN  5376
#define BH    6144
#define BH1V  34816
#define BR2   38912
#define BSL   43008
#define BSG   54272
#define SMEM_BYTES 57344
#define WSL (BSL/4)
#define WSG (BSG/4)

__global__ void __launch_bounds__(256,2)
accel_mma_kernel(int S, const float* __restrict__ obs, const float* __restrict__ action,
    float* __restrict__ out,
    const float* __restrict__ b2L, const float* __restrict__ b3L,
    const float* __restrict__ b2V, const float* __restrict__ W3V, int B)
{
  extern __shared__ char smc[];
  float* smf=(float*)smc;
  const int tid=threadIdx.x, w=tid>>5, lane=tid&31;
  const int gid=lane>>2, tig=lane&3;
  const int eb=blockIdx.x*16;
  const int vm=g_viol[S];
  const unsigned smb=(unsigned)__cvta_generic_to_shared(smc);

  const int sub=lane>>3, l7=lane&7;
  const int lm_row=l7+((sub&1)<<3);
  const int chunk=sub>>1;
  const int r7=l7;
  const unsigned aA0 = smb + BA0 + lm_row*48 + chunk*16;
  const unsigned aVIN= smb + BVIN + lm_row*48 + chunk*16;
  const unsigned rbH  = smb + BH   + lm_row*256;
  const unsigned rbH1V= smb + BH1V + lm_row*256;
  const unsigned rbR2 = smb + BR2  + lm_row*256;

  // ---------- P0: build A matrices (row = ch*16 + el) ----------
  if (tid<112){
    int row=tid, ch=row>>4, el=row&15;
    int e=eb+el; if (e>=B) e=B-1;
    float t16[16];
#pragma unroll
    for(int k=0;k<16;k++) t16[k]=0.f;
    if (ch==0){
#pragma unroll
      for(int j=0;j<6;j++){ float qj=g_qs[S][e*6+j]; t16[2*j]=cosf(qj); t16[2*j+1]=sinf(qj); }
      t16[12]=1.f;
    } else {
      int p=ch-1; float qp=g_qs[S][e*6+p];
      t16[2*p]=-sinf(qp); t16[2*p+1]=cosf(qp);
    }
    __half2* dst=(__half2*)(smc+BA0+row*48);
#pragma unroll
    for(int k=0;k<8;k++) dst[k]=__floats2half2_rn(t16[2*k],t16[2*k+1]);
    if (ch==0){
      __half2* dv=(__half2*)(smc+BVIN+el*48);
#pragma unroll
      for(int k=0;k<8;k++) dv[k]=__floats2half2_rn(t16[2*k],t16[2*k+1]);
    }
  }
  __syncthreads();

  // ---------- P1: V layer1 + L layer1 (K=16) ----------
  {
    float DV[2][4]={};
    {
      unsigned a0,a1,a2,a3; ldsm4(a0,a1,a2,a3,aVIN);
#pragma unroll
      for(int nt=0;nt<2;nt++){
        uint2 bf=__ldg(&g_W1V[(w*16+nt*8+gid)*4+tig]);
        mma16(DV[nt],a0,a1,a2,a3,bf.x,bf.y);
      }
    }
#pragma unroll
    for(int nt=0;nt<2;nt++){
      int c0=w*16+nt*8+tig*2;
      *(__half2*)(smc+BH1V+hswz(gid,c0))  =__floats2half2_rn(sp_f(DV[nt][0]),sp_f(DV[nt][1]));
      *(__half2*)(smc+BH1V+hswz(gid+8,c0))=__floats2half2_rn(sp_f(DV[nt][2]),sp_f(DV[nt][3]));
    }
    float D1[7][2][4]={};
#pragma unroll
    for(int m=0;m<7;m++){
      unsigned a0,a1,a2,a3; ldsm4(a0,a1,a2,a3,aA0+m*768);
#pragma unroll
      for(int nt=0;nt<2;nt++){
        uint2 bf=__ldg(&g_W1L[(w*16+nt*8+gid)*4+tig]);
        mma16(D1[m][nt],a0,a1,a2,a3,bf.x,bf.y);
      }
    }
    float sgr[2][4];
#pragma unroll
    for(int nt=0;nt<2;nt++){
      int c0=w*16+nt*8+tig*2;
#pragma unroll
      for(int i=0;i<4;i++) sgr[nt][i]=sg_f(D1[0][nt][i]);
      *(__half2*)(smc+BH+hswz(gid,c0))  =__floats2half2_rn(sp_f(D1[0][nt][0]),sp_f(D1[0][nt][1]));
      *(__half2*)(smc+BH+hswz(gid+8,c0))=__floats2half2_rn(sp_f(D1[0][nt][2]),sp_f(D1[0][nt][3]));
    }
#pragma unroll
    for(int m=1;m<7;m++)
#pragma unroll
      for(int nt=0;nt<2;nt++){
        int c0=w*16+nt*8+tig*2;
        *(__half2*)(smc+BH+hswz(m*16+gid,c0))  =__floats2half2_rn(sgr[nt][0]*D1[m][nt][0],sgr[nt][1]*D1[m][nt][1]);
        *(__half2*)(smc+BH+hswz(m*16+8+gid,c0))=__floats2half2_rn(sgr[nt][2]*D1[m][nt][2],sgr[nt][3]*D1[m][nt][3]);
      }
  }
  __syncthreads();

  // ---------- P2: V layer2 then L layer2 (R13 separated loops) ----------
  {
    float DV[2][4]={};
#pragma unroll
    for(int ktp=0;ktp<8;ktp++){
      unsigned a0,a1,a2,a3; ldsm4(a0,a1,a2,a3, rbH1V + (((2*ktp+chunk)^r7)<<4));
#pragma unroll
      for(int nt=0;nt<2;nt++){
        uint2 bf=__ldg(&g_W2V[((w*16+nt*8+gid)*8+ktp)*4+tig]);
        mma16(DV[nt],a0,a1,a2,a3,bf.x,bf.y);
      }
    }
#pragma unroll
    for(int nt=0;nt<2;nt++){
      int c0=w*16+nt*8+tig*2;
      float bv0=__ldg(b2V+c0),bv1=__ldg(b2V+c0+1),w30=__ldg(W3V+c0),w31=__ldg(W3V+c0+1);
      *(__half2*)(smc+BR2+hswz(gid,c0))  =__floats2half2_rn(w30*sg_f(DV[nt][0]+bv0),w31*sg_f(DV[nt][1]+bv1));
      *(__half2*)(smc+BR2+hswz(gid+8,c0))=__floats2half2_rn(w30*sg_f(DV[nt][2]+bv0),w31*sg_f(DV[nt][3]+bv1));
    }
    float D2[7][2][4]={};
#pragma unroll 2
    for(int ktp=0;ktp<8;ktp++){
      uint2 bf[2];
#pragma unroll
      for(int nt=0;nt<2;nt++) bf[nt]=__ldg(&g_W2L[((w*16+nt*8+gid)*8+ktp)*4+tig]);
      unsigned koff=(((unsigned)(2*ktp+chunk)^r7)<<4);
#pragma unroll
      for(int m=0;m<7;m++){
        unsigned a0,a1,a2,a3; ldsm4(a0,a1,a2,a3, rbH + m*4096 + koff);
#pragma unroll
        for(int nt=0;nt<2;nt++) mma16(D2[m][nt],a0,a1,a2,a3,bf[nt].x,bf[nt].y);
      }
    }
    __syncthreads();   // all warps done reading H
    float sgr[2][4];
#pragma unroll
    for(int nt=0;nt<2;nt++){
      int c0=w*16+nt*8+tig*2;
      float b0=__ldg(b2L+c0), b1=__ldg(b2L+c0+1);
      float z0=D2[0][nt][0]+b0, z1=D2[0][nt][1]+b1, z2=D2[0][nt][2]+b0, z3=D2[0][nt][3]+b1;
      sgr[nt][0]=sg_f(z0); sgr[nt][1]=sg_f(z1); sgr[nt][2]=sg_f(z2); sgr[nt][3]=sg_f(z3);
      *(__half2*)(smc+BH+hswz(gid,c0))  =__floats2half2_rn(sp_f(z0),sp_f(z1));
      *(__half2*)(smc+BH+hswz(gid+8,c0))=__floats2half2_rn(sp_f(z2),sp_f(z3));
    }
#pragma unroll
    for(int m=1;m<7;m++)
#pragma unroll
      for(int nt=0;nt<2;nt++){
        int c0=w*16+nt*8+tig*2;
        *(__half2*)(smc+BH+hswz(m*16+gid,c0))  =__floats2half2_rn(sgr[nt][0]*D2[m][nt][0],sgr[nt][1]*D2[m][nt][1]);
        *(__half2*)(smc+BH+hswz(m*16+8+gid,c0))=__floats2half2_rn(sgr[nt][2]*D2[m][nt][2],sgr[nt][3]*D2[m][nt][3]);
      }
  }
  __syncthreads();

  // ---------- P3: L layer3 on 6 warps (2M x 3N) | V backward+grad on w6-7 ----------
  if (w<6){
    const int wm=(w>=3)?1:0, wn=w-3*wm;
    // wm0: tiles {0,1,2,3}; wm1: tiles {0,4,5,6} (tile0 recomputed for sigmoid, not stored)
    float D3[4][4]={};
#pragma unroll 2
    for(int ktp=0;ktp<8;ktp++){
      uint2 bf=__ldg(&g_W3L[((wn*8+gid)*8+ktp)*4+tig]);
      unsigned koff=(((unsigned)(2*ktp+chunk)^r7)<<4);
#pragma unroll
      for(int mi=0;mi<4;mi++){
        int m=wm?((mi==0)?0:(mi+3)):mi;
        unsigned a0,a1,a2,a3; ldsm4(a0,a1,a2,a3, rbH + m*4096 + koff);
        mma16(D3[mi],a0,a1,a2,a3,bf.x,bf.y);
      }
    }
    int c0=wn*8+tig*2;
    float bb0=(c0<21)?__ldg(b3L+c0):0.f, bb1=(c0+1<21)?__ldg(b3L+c0+1):0.f;
    float z0=D3[0][0]+bb0, z1=D3[0][1]+bb1, z2=D3[0][2]+bb0, z3=D3[0][3]+bb1;
    float sg0=sg_f(z0),sg1=sg_f(z1),sg2=sg_f(z2),sg3=sg_f(z3);
    if (wm==0){
      smf[WSL+gid*176+c0]=sp_f(z0);      smf[WSL+gid*176+c0+1]=sp_f(z1);
      smf[WSL+(gid+8)*176+c0]=sp_f(z2);  smf[WSL+(gid+8)*176+c0+1]=sp_f(z3);
    }
#pragma unroll
    for(int mi=1;mi<4;mi++){
      int m=wm?(mi+3):mi;
      smf[WSL+gid*176+m*25+c0]=sg0*D3[mi][0];      smf[WSL+gid*176+m*25+c0+1]=sg1*D3[mi][1];
      smf[WSL+(gid+8)*176+m*25+c0]=sg2*D3[mi][2];  smf[WSL+(gid+8)*176+m*25+c0+1]=sg3*D3[mi][3];
    }
  } else {
    const int wv=w-6;   // 0 or 1, owns 64 N-columns
    float DB[8][4]={};
#pragma unroll 2
    for(int ktp=0;ktp<8;ktp++){
      unsigned a0,a1,a2,a3; ldsm4(a0,a1,a2,a3, rbR2 + (((2*ktp+chunk)^r7)<<4));
#pragma unroll
      for(int nt=0;nt<8;nt++){
        int n=wv*64+nt*8+gid;            // n <= 127
        uint2 bf=__ldg(&g_W2VT[(n*8+ktp)*4+tig]);
        mma16(DB[nt],a0,a1,a2,a3,bf.x,bf.y);
      }
    }
#pragma unroll
    for(int nt=0;nt<8;nt++){
      int c0=wv*64+nt*8+tig*2;           // c0 <= 126
      float2 hA=__half22float2(*(__half2*)(smc+BH1V+hswz(gid,c0)));
      float2 hB=__half22float2(*(__half2*)(smc+BH1V+hswz(gid+8,c0)));
      float r0=DB[nt][0]*(1.f-__expf(-hA.x)), r1=DB[nt][1]*(1.f-__expf(-hA.y));
      float r2=DB[nt][2]*(1.f-__expf(-hB.x)), r3=DB[nt][3]*(1.f-__expf(-hB.y));
      *(__half2*)(smc+BH1V+hswz(gid,c0))  =__floats2half2_rn(r0,r1);
      *(__half2*)(smc+BH1V+hswz(gid+8,c0))=__floats2half2_rn(r2,r3);
    }
    __syncwarp();
    // K-split grad partial: this warp's 4 ktp slots read only its own H1V half
    float DG[2][4]={};
#pragma unroll
    for(int t=0;t<4;t++){
      int ktp=wv*4+t;
      unsigned a0,a1,a2,a3; ldsm4(a0,a1,a2,a3, rbH1V + (((2*ktp+chunk)^r7)<<4));
#pragma unroll
      for(int nt=0;nt<2;nt++){
        uint2 bf=__ldg(&g_W1VT[((nt*8+gid)*8+ktp)*4+tig]);
        mma16(DG[nt],a0,a1,a2,a3,bf.x,bf.y);
      }
    }
#pragma unroll
    for(int nt=0;nt<2;nt++){
      int c=nt*8+tig*2;
      if (c<12){ smf[WSG+wv*192+gid*12+c]=DG[nt][0]; smf[WSG+wv*192+(gid+8)*12+c]=DG[nt][2]; }
      if (c+1<12){ smf[WSG+wv*192+gid*12+c+1]=DG[nt][1]; smf[WSG+wv*192+(gid+8)*12+c+1]=DG[nt][3]; }
    }
  }
  __syncthreads();

  // ---------- P5: assembly + Cholesky solve (warps 0-3, 8 lanes/element) ----------
  if (w<4){
    int gl=lane&7, grp=lane>>3, eloc=w*4+grp;
    int e=eb+eloc; bool valid=(e<B); if(!valid) e=B-1;
    const float* SLe=smf+WSL+eloc*176;
    float* SDel=smf+eloc*24;
    float qd6[6];
#pragma unroll
    for(int j=0;j<6;j++) qd6[j]=g_qds[S][e*6+j];
    if (gl<7){
#pragma unroll
      for(int t=0;t<3;t++){
        int m=gl*3+t;
        if (m<21){
          float s=0.f;
#pragma unroll
          for(int p=0;p<6;p++) s+=qd6[p]*SLe[(1+p)*25+m];
          SDel[m]=s;
        }
      }
    }
    __syncwarp();
    int li=(gl<6)?gl:5;
    float w6[6],u6[6],Dq[6];
#pragma unroll
    for(int k=0;k<6;k++){
      float sw=0.f,su=0.f,sd=0.f;
#pragma unroll
      for(int i2=0;i2<6;i2++) if (i2>=k){
        int m=TRI(i2,k); float a=qd6[i2];
        sw+=SLe[m]*a; su+=SLe[(1+li)*25+m]*a; sd+=SDel[m]*a;
      }
      w6[k]=sw; u6[k]=su; Dq[k]=sd;
    }
    float term2=0.f;
#pragma unroll
    for(int k=0;k<6;k++) term2+=w6[k]*u6[k];
    int base=li*(li+1)/2;
    float Dw=0.f,LDq=0.f;
#pragma unroll
    for(int j2=0;j2<6;j2++) if (j2<=li){ Dw+=SDel[base+j2]*w6[j2]; LDq+=SLe[base+j2]*Dq[j2]; }
    float ci=Dw+LDq-term2;
    float qsi=g_qs[S][e*6+li];
    float gx=smf[WSG+eloc*12+2*li]+smf[WSG+192+eloc*12+2*li];
    float gy=smf[WSG+eloc*12+2*li+1]+smf[WSG+192+eloc*12+2*li+1];
    float gi=-gx*sinf(qsi)+gy*cosf(qsi);
    float lo=c_LOWER[li]+0.1f, up=c_UPPER[li]-0.1f;
    float fi;
    if ((vm>>li)&1) fi=(qsi<=lo)?c_EFFORT[li]:((qsi>=up)?-c_EFFORT[li]:0.f);
    else            fi=-5.f*(1.f/(qsi-lo)-1.f/(up-qsi));
    float tau=__ldg(action+e*6+li)*c_EFFORT[li];
    float rhs=tau-ci-gi-fi;
    int gb=lane&~7;
    float accf=rhs, yvv=0.f;
#pragma unroll
    for(int j2=0;j2<6;j2++){
      float yj=__shfl_sync(FULLMASK,accf,gb+j2)/SLe[TRI(j2,j2)];
      if (gl==j2) yvv=yj;
      if (gl>j2 && gl<6) accf-=SLe[base+j2]*yj;
    }
    float acc2=yvv, xi=0.f;
#pragma unroll
    for(int j2=5;j2>=0;j2--){
      float xj=__shfl_sync(FULLMASK,acc2,gb+j2)/SLe[TRI(j2,j2)];
      if (gl==j2) xi=xj;
      if (gl<j2) acc2-=SLe[TRI(j2,gl)]*xj;
    }

    if (S<3){
      if (gl<6 && valid) g_kqd[S][e*6+gl]=xi;
      unsigned bits=0;
      if (gl<6 && valid){
        float q0=obs[e*12+gl], qd0=obs[e*12+6+gl];
        float qs,qds;
        if (S==0){ qs=q0+0.5f*DT*qd0;                 qds=qd0+0.5f*DT*xi; }
        else if (S==1){ qs=q0+0.5f*DT*g_qds[1][e*6+gl]; qds=qd0+0.5f*DT*xi; }
        else          { qs=q0+DT*g_qds[2][e*6+gl];      qds=qd0+DT*xi; }
        g_qs[S+1][e*6+gl]=qs; g_qds[S+1][e*6+gl]=qds;
        float lo2=c_LOWER[gl]+0.1f, up2=c_UPPER[gl]-0.1f;
        if (qs<=lo2 || qs>=up2) bits=1u<<gl;
      }
      unsigned r=__reduce_or_sync(FULLMASK,bits);
      if (lane==0 && r) atomicOr(&g_viol[S+1],(int)r);
    } else {
      if (gl<6 && valid){
        int idx=e*6+gl;
        float q0=obs[e*12+gl], qd0=obs[e*12+6+gl];
        float k0=g_kqd[0][idx],k1=g_kqd[1][idx],k2=g_kqd[2][idx];
        const float c1=DT/6.f;
        float qn=q0+c1*(g_qds[0][idx]+2.f*g_qds[1][idx]+2.f*g_qds[2][idx]+g_qds[3][idx]);
        qn=fminf(fmaxf(qn,c_LOWER[gl]),c_UPPER[gl]);
        float qdn=qd0+c1*(k0+2.f*k1+2.f*k2+xi);
        out[e*12+gl]=qn;
        out[e*12+6+gl]=qdn;
      }
    }
  }
}

extern "C" void kernel_launch(void* const* d_in, const int* in_sizes, int n_in,
                              void* d_out, int out_size)
{
  const float* obs   =(const float*)d_in[0];
  const float* action=(const float*)d_in[1];
  const float* W1L=(const float*)d_in[2];  const float* b1L=(const float*)d_in[3];
  const float* W2L=(const float*)d_in[4];  const float* b2L=(const float*)d_in[5];
  const float* W3L=(const float*)d_in[6];  const float* b3L=(const float*)d_in[7];
  const float* W1V=(const float*)d_in[8];  const float* b1V=(const float*)d_in[9];
  const float* W2V=(const float*)d_in[10]; const float* b2V=(const float*)d_in[11];
  const float* W3V=(const float*)d_in[12]; const float* b3V=(const float*)d_in[13];
  (void)b3V;
  float* out=(float*)d_out;
  int B=in_sizes[0]/12;
  if (B>MAXB) B=MAXB;

  cudaFuncSetAttribute(accel_mma_kernel, cudaFuncAttributeMaxDynamicSharedMemorySize, SMEM_BYTES);

  int nbA=(B+15)/16;
  int nbI=(B*6+255)/256; if (nbI<57) nbI=57;

  zero_viol_kernel<<<1,32>>>();
  init_kernel<<<nbI,256>>>(obs,W1L,b1L,W2L,W3L,W1V,b1V,W2V,B);
  for (int s=0;s<4;s++){
    accel_mma_kernel<<<nbA,256,SMEM_BYTES>>>(s,obs,action,out,b2L,b3L,b2V,W3V,B);
  }
}